// round 1
// baseline (speedup 1.0000x reference)
#include <cuda_runtime.h>
#include <cuda_bf16.h>

// Problem constants (fixed by the reference)
#define NN 4096
#define KK 32
#define DD 256
#define HH 128
#define GG 384   // 3*H

typedef unsigned long long ull;

// ---------------- device scratch (no allocations allowed) ----------------
static __device__ float4 g_wih0p[64 * GG];   // W_ih0 packed [k4][g], k4 in 0..63
static __device__ float4 g_whh0p[32 * GG];   // W_hh0 packed
static __device__ float4 g_wih1p[32 * GG];   // W_ih1 packed
static __device__ float4 g_whh1p[32 * GG];   // W_hh1 packed
static __device__ float  g_xw0[NN * GG];     // x @ W_ih0^T + b_ih0   (6.3 MB)
static __device__ int    g_sorted[NN];
static __device__ int    g_off[KK + 1];
static __device__ int    g_len[KK];
static __device__ float  g_emb[KK * HH];
static __device__ float  g_wn[GG];
static __device__ float  g_scores[NN];
static __device__ float  g_clusum[KK];

// ---------------- f32x2 packed-FMA helpers ----------------
static __device__ __forceinline__ ull ffma2(ull a, ull b, ull c) {
    ull d;
    asm("fma.rn.f32x2 %0, %1, %2, %3;" : "=l"(d) : "l"(a), "l"(b), "l"(c));
    return d;
}
static __device__ __forceinline__ float f2sum(ull v) {
    float a, b;
    asm("mov.b64 {%0, %1}, %2;" : "=f"(a), "=f"(b) : "l"(v));
    return a + b;
}
static __device__ __forceinline__ float sigmoidf_(float x) {
    return 1.0f / (1.0f + expf(-x));
}

// ---------------- kernel: cluster ordering (stable) ----------------
__global__ void k_setup(const int* __restrict__ labels) {
    __shared__ int ls[NN];
    for (int i = threadIdx.x; i < NN; i += blockDim.x) ls[i] = labels[i];
    __syncthreads();
    if (threadIdx.x < 32) {
        int k = threadIdx.x;
        const int4* l4 = reinterpret_cast<const int4*>(ls);
        int cnt = 0;
        for (int ii = 0; ii < NN / 4; ++ii) {
            int4 v = l4[ii];
            cnt += (v.x == k) + (v.y == k) + (v.z == k) + (v.w == k);
        }
        g_len[k] = cnt;
        // warp exclusive prefix
        int v = cnt;
        #pragma unroll
        for (int d = 1; d < 32; d <<= 1) {
            int y = __shfl_up_sync(0xffffffffu, v, d);
            if (k >= d) v += y;
        }
        int off = v - cnt;
        g_off[k] = off;
        if (k == 31) g_off[32] = off + cnt;
        // stable scatter
        int c = off;
        for (int ii = 0; ii < NN / 4; ++ii) {
            int4 q = l4[ii];
            if (q.x == k) g_sorted[c++] = 4 * ii;
            if (q.y == k) g_sorted[c++] = 4 * ii + 1;
            if (q.z == k) g_sorted[c++] = 4 * ii + 2;
            if (q.w == k) g_sorted[c++] = 4 * ii + 3;
        }
    }
}

// ---------------- kernel: pack weights [g][k] -> [k4][g] float4 ----------------
__global__ void k_pack(const float* __restrict__ wih0, const float* __restrict__ whh0,
                       const float* __restrict__ wih1, const float* __restrict__ whh1) {
    int b = blockIdx.x;
    int g = threadIdx.x;
    const float* src;
    float4* dst;
    int k4, Kdim;
    if (b < 64)       { src = wih0; dst = g_wih0p; k4 = b;       Kdim = DD; }
    else if (b < 96)  { src = whh0; dst = g_whh0p; k4 = b - 64;  Kdim = HH; }
    else if (b < 128) { src = wih1; dst = g_wih1p; k4 = b - 96;  Kdim = HH; }
    else              { src = whh1; dst = g_whh1p; k4 = b - 128; Kdim = HH; }
    const float* row = src + (size_t)g * Kdim + k4 * 4;
    dst[k4 * GG + g] = make_float4(row[0], row[1], row[2], row[3]);
}

// ---------------- kernel: xw0 = x @ W_ih0^T + b_ih0 ----------------
__global__ void __launch_bounds__(384) k_xw0(const float* __restrict__ x,
                                             const float* __restrict__ b_ih0) {
    __shared__ __align__(16) float xs[16 * DD];   // 16 KB
    int r0 = blockIdx.x * 16;
    {
        const float4* xsrc = reinterpret_cast<const float4*>(x + (size_t)r0 * DD);
        float4* xd = reinterpret_cast<float4*>(xs);
        for (int i = threadIdx.x; i < 16 * DD / 4; i += 384) xd[i] = xsrc[i];
    }
    __syncthreads();
    int g = threadIdx.x;
    ull acc[16];
    #pragma unroll
    for (int s = 0; s < 16; ++s) acc[s] = 0ull;
    const ulonglong2* W = reinterpret_cast<const ulonglong2*>(g_wih0p) + g;
    #pragma unroll 8
    for (int k4 = 0; k4 < 64; ++k4) {
        ulonglong2 w = W[k4 * GG];
        #pragma unroll
        for (int s = 0; s < 16; ++s) {
            ulonglong2 xv = *reinterpret_cast<const ulonglong2*>(&xs[s * DD + k4 * 4]);
            acc[s] = ffma2(w.x, xv.x, acc[s]);
            acc[s] = ffma2(w.y, xv.y, acc[s]);
        }
    }
    float bi = b_ih0[g];
    #pragma unroll
    for (int s = 0; s < 16; ++s)
        g_xw0[(size_t)(r0 + s) * GG + g] = f2sum(acc[s]) + bi;
}

// ---------------- kernel: the GRU recurrence (2 clusters per block) ----------------
__global__ void __launch_bounds__(384, 1) k_rec(const float* __restrict__ b_ih0,
                                                const float* __restrict__ b_hh0,
                                                const float* __restrict__ b_ih1,
                                                const float* __restrict__ b_hh1) {
    __shared__ __align__(16) float h1s[2][HH];
    __shared__ __align__(16) float h2s[2][HH];
    __shared__ float hw0s[2][GG];
    __shared__ float hw1s[2][GG];
    __shared__ float xw1s[2][GG];

    int g  = threadIdx.x;
    int c0 = blockIdx.x;
    int c1 = blockIdx.x + 16;

    int len0 = g_len[c0], len1 = g_len[c1];
    int off0 = g_off[c0], off1 = g_off[c1];
    int le0 = max(len0, 1), le1 = max(len1, 1);
    int tmax = max(le0, le1);

    if (g < HH) { h1s[0][g] = 0.f; h1s[1][g] = 0.f; h2s[0][g] = 0.f; h2s[1][g] = 0.f; }
    float bh0 = b_hh0[g];
    float bi1 = b_ih1[g];
    float bh1 = b_hh1[g];
    __syncthreads();

    const ulonglong2* Whh0 = reinterpret_cast<const ulonglong2*>(g_whh0p) + g;
    const ulonglong2* Wih1 = reinterpret_cast<const ulonglong2*>(g_wih1p) + g;
    const ulonglong2* Whh1 = reinterpret_cast<const ulonglong2*>(g_whh1p) + g;

    for (int t = 0; t < tmax; ++t) {
        // ---- P1: hw0 = W_hh0 @ h1 (old), hw1 = W_hh1 @ h2 (old), both clusters
        ull a00 = 0ull, a01 = 0ull, a10 = 0ull, a11 = 0ull;
        #pragma unroll
        for (int k4 = 0; k4 < 32; ++k4) {
            ulonglong2 w0 = Whh0[k4 * GG];
            ulonglong2 w1 = Whh1[k4 * GG];
            ulonglong2 hA0 = *reinterpret_cast<const ulonglong2*>(&h1s[0][k4 * 4]);
            ulonglong2 hA1 = *reinterpret_cast<const ulonglong2*>(&h1s[1][k4 * 4]);
            ulonglong2 hB0 = *reinterpret_cast<const ulonglong2*>(&h2s[0][k4 * 4]);
            ulonglong2 hB1 = *reinterpret_cast<const ulonglong2*>(&h2s[1][k4 * 4]);
            a00 = ffma2(w0.x, hA0.x, a00); a00 = ffma2(w0.y, hA0.y, a00);
            a01 = ffma2(w0.x, hA1.x, a01); a01 = ffma2(w0.y, hA1.y, a01);
            a10 = ffma2(w1.x, hB0.x, a10); a10 = ffma2(w1.y, hB0.y, a10);
            a11 = ffma2(w1.x, hB1.x, a11); a11 = ffma2(w1.y, hB1.y, a11);
        }
        hw0s[0][g] = f2sum(a00) + bh0;
        hw0s[1][g] = f2sum(a01) + bh0;
        hw1s[0][g] = f2sum(a10) + bh1;
        hw1s[1][g] = f2sum(a11) + bh1;
        __syncthreads();

        // ---- P2: layer-0 gate update -> h1 (new)
        if (g < 2 * HH) {
            int c = g >> 7, j = g & (HH - 1);
            int len = c ? len1 : len0;
            int le  = c ? le1  : le0;
            int off = c ? off1 : off0;
            if (t < le) {
                float xr, xz, xn;
                if (t < len) {
                    int idx = g_sorted[off + t];
                    const float* xwp = g_xw0 + (size_t)idx * GG;
                    xr = xwp[j]; xz = xwp[HH + j]; xn = xwp[2 * HH + j];
                } else {  // empty cluster: one step with x = 0
                    xr = b_ih0[j]; xz = b_ih0[HH + j]; xn = b_ih0[2 * HH + j];
                }
                float r = sigmoidf_(xr + hw0s[c][j]);
                float z = sigmoidf_(xz + hw0s[c][HH + j]);
                float n = tanhf(xn + r * hw0s[c][2 * HH + j]);
                h1s[c][j] = (1.0f - z) * n + z * h1s[c][j];
            }
        }
        __syncthreads();

        // ---- P3: xw1 = W_ih1 @ h1 (new), both clusters
        ull b0 = 0ull, b1 = 0ull;
        #pragma unroll
        for (int k4 = 0; k4 < 32; ++k4) {
            ulonglong2 w = Wih1[k4 * GG];
            ulonglong2 p0 = *reinterpret_cast<const ulonglong2*>(&h1s[0][k4 * 4]);
            ulonglong2 p1 = *reinterpret_cast<const ulonglong2*>(&h1s[1][k4 * 4]);
            b0 = ffma2(w.x, p0.x, b0); b0 = ffma2(w.y, p0.y, b0);
            b1 = ffma2(w.x, p1.x, b1); b1 = ffma2(w.y, p1.y, b1);
        }
        xw1s[0][g] = f2sum(b0) + bi1;
        xw1s[1][g] = f2sum(b1) + bi1;
        __syncthreads();

        // ---- P4: layer-1 gate update -> h2 (new)
        if (g < 2 * HH) {
            int c = g >> 7, j = g & (HH - 1);
            int le = c ? le1 : le0;
            if (t < le) {
                float r = sigmoidf_(xw1s[c][j] + hw1s[c][j]);
                float z = sigmoidf_(xw1s[c][HH + j] + hw1s[c][HH + j]);
                float n = tanhf(xw1s[c][2 * HH + j] + r * hw1s[c][2 * HH + j]);
                h2s[c][j] = (1.0f - z) * n + z * h2s[c][j];
            }
        }
        __syncthreads();
    }

    if (g < 2 * HH) {
        int c = g >> 7, j = g & (HH - 1);
        g_emb[(c ? c1 : c0) * HH + j] = h2s[c][j];
    }
}

// ---------------- kernel: weight-normed linear weights ----------------
__global__ void k_wn(const float* __restrict__ lin_v, const float* __restrict__ lin_g) {
    __shared__ float red[512];
    int g = threadIdx.x;  // 384 threads
    float v = lin_v[g];
    red[g] = v * v;
    if (g < 128) red[384 + g] = 0.f;
    __syncthreads();
    #pragma unroll
    for (int s = 256; s >= 1; s >>= 1) {
        if (g < s) red[g] += red[g + s];
        __syncthreads();
    }
    float invn = 1.0f / sqrtf(red[0]);
    g_wn[g] = lin_g[0] * v * invn;
}

// ---------------- kernel: per-sentence tanh scores ----------------
__global__ void __launch_bounds__(128) k_score(const float* __restrict__ x,
                                               const int* __restrict__ labels,
                                               const float* __restrict__ lin_b) {
    __shared__ __align__(16) float wns[GG];
    __shared__ __align__(16) float embs[KK][132];  // padded to dodge bank conflicts
    for (int i = threadIdx.x; i < GG; i += 128) wns[i] = g_wn[i];
    for (int i = threadIdx.x; i < KK * HH; i += 128) embs[i >> 7][i & 127] = g_emb[i];
    __syncthreads();
    int i = blockIdx.x * 128 + threadIdx.x;
    int lab = labels[i];
    const float4* xr = reinterpret_cast<const float4*>(x) + (size_t)i * (DD / 4);
    float acc = 0.f;
    #pragma unroll 8
    for (int k4 = 0; k4 < DD / 4; ++k4) {
        float4 xv = xr[k4];
        float4 wv = *reinterpret_cast<const float4*>(&wns[k4 * 4]);
        acc = fmaf(xv.x, wv.x, acc); acc = fmaf(xv.y, wv.y, acc);
        acc = fmaf(xv.z, wv.z, acc); acc = fmaf(xv.w, wv.w, acc);
    }
    #pragma unroll 8
    for (int k4 = 0; k4 < HH / 4; ++k4) {
        float4 ev = *reinterpret_cast<const float4*>(&embs[lab][k4 * 4]);
        float4 wv = *reinterpret_cast<const float4*>(&wns[DD + k4 * 4]);
        acc = fmaf(ev.x, wv.x, acc); acc = fmaf(ev.y, wv.y, acc);
        acc = fmaf(ev.z, wv.z, acc); acc = fmaf(ev.w, wv.w, acc);
    }
    g_scores[i] = tanhf(acc + lin_b[0]);
}

// ---------------- kernel: deterministic per-cluster score sums ----------------
__global__ void __launch_bounds__(128) k_clusum() {
    __shared__ float red[128];
    int k = blockIdx.x;
    int len = g_len[k], off = g_off[k];
    float s = 0.f;
    for (int t = threadIdx.x; t < len; t += 128) s += g_scores[g_sorted[off + t]];
    red[threadIdx.x] = s;
    __syncthreads();
    #pragma unroll
    for (int d = 64; d >= 1; d >>= 1) {
        if (threadIdx.x < d) red[threadIdx.x] += red[threadIdx.x + d];
        __syncthreads();
    }
    if (threadIdx.x == 0) g_clusum[k] = red[0];
}

// ---------------- kernel: final blend ----------------
__global__ void k_final(const int* __restrict__ labels, float* __restrict__ out) {
    int i = blockIdx.x * blockDim.x + threadIdx.x;
    if (i >= NN) return;
    const float INV = 0.0625f;  // 1 / 4096^(1/3)
    float sal = g_scores[i] / g_clusum[labels[i]];
    float pos = fmaxf(0.5f, expf(-((float)(i + 1)) * INV));
    out[i] = 0.5f * sal + 0.5f * pos;
}

// ---------------- launch ----------------
extern "C" void kernel_launch(void* const* d_in, const int* in_sizes, int n_in,
                              void* d_out, int out_size) {
    const float* x      = (const float*)d_in[0];
    const int*   labels = (const int*)d_in[1];
    const float* W_ih0  = (const float*)d_in[2];
    const float* W_hh0  = (const float*)d_in[3];
    const float* b_ih0  = (const float*)d_in[4];
    const float* b_hh0  = (const float*)d_in[5];
    const float* W_ih1  = (const float*)d_in[6];
    const float* W_hh1  = (const float*)d_in[7];
    const float* b_ih1  = (const float*)d_in[8];
    const float* b_hh1  = (const float*)d_in[9];
    const float* lin_v  = (const float*)d_in[10];
    const float* lin_g  = (const float*)d_in[11];
    const float* lin_b  = (const float*)d_in[12];
    float* out = (float*)d_out;

    k_setup<<<1, 256>>>(labels);
    k_pack<<<160, 384>>>(W_ih0, W_hh0, W_ih1, W_hh1);
    k_xw0<<<NN / 16, 384>>>(x, b_ih0);
    k_rec<<<16, 384>>>(b_ih0, b_hh0, b_ih1, b_hh1);
    k_wn<<<1, 384>>>(lin_v, lin_g);
    k_score<<<NN / 128, 128>>>(x, labels, lin_b);
    k_clusum<<<KK, 128>>>();
    k_final<<<16, 256>>>(labels, out);
}